// round 3
// baseline (speedup 1.0000x reference)
#include <cuda_runtime.h>
#include <cstdint>

#define T_DIM 512
#define B_DIM 512
#define I_DIM 100
#define H_DIM 96
#define G_DIM 288   // 3*H

// Scratch for input projections: [dir][t][b][3H]  (604 MB, static device alloc — allowed)
__device__ float g_xp[2][T_DIM][B_DIM][G_DIM];

// ---------------------------------------------------------------------------
// packed f32x2 FMA (Blackwell): d.lo = a.lo*b.lo+c.lo ; d.hi = a.hi*b.hi+c.hi
// ---------------------------------------------------------------------------
__device__ __forceinline__ float2 ffma2(float2 a, float2 b, float2 c) {
    float2 d;
    asm("fma.rn.f32x2 %0, %1, %2, %3;"
        : "=l"(*reinterpret_cast<unsigned long long*>(&d))
        : "l"(*reinterpret_cast<unsigned long long*>(&a)),
          "l"(*reinterpret_cast<unsigned long long*>(&b)),
          "l"(*reinterpret_cast<unsigned long long*>(&c)));
    return d;
}

__device__ __forceinline__ float sigmoidf_fast(float x) {
    return __fdividef(1.0f, 1.0f + __expf(-x));
}
__device__ __forceinline__ float tanhf_fast(float x) {
    return 2.0f * __fdividef(1.0f, 1.0f + __expf(-2.0f * x)) - 1.0f;
}

// ---------------------------------------------------------------------------
// Kernel 1: input projection  xp[dir][t][b][g] = sum_k x[t][b][k]*W_ih[g][k] + b_ih[g]
// grid (148, 2), block 288. Thread g owns one output column; 64-row tiles.
// W transposed into smem [k][g] (stride 289: conflict-free both ways),
// x tile transposed into smem [k][r] (stride 68, 16B-aligned for LDS.128).
// ---------------------------------------------------------------------------
#define PROJ_TM 64
#define WS_STRIDE 289
#define XS_STRIDE 68

extern __shared__ float proj_sm[];

__global__ void __launch_bounds__(288, 1)
proj_kernel(const float* __restrict__ x,
            const float* __restrict__ w_f, const float* __restrict__ b_f,
            const float* __restrict__ w_b, const float* __restrict__ b_b)
{
    float* Ws = proj_sm;                       // [100][289]
    float* Xs = proj_sm + I_DIM * WS_STRIDE;   // [100][68]

    const int dir = blockIdx.y;
    const float* __restrict__ W    = dir ? w_b : w_f;
    const float* __restrict__ bias = dir ? b_b : b_f;
    const int tid = threadIdx.x;
    const int g   = tid;   // 0..287

    // Load W transposed: Ws[k][g] = W[g][k]
    for (int idx = tid; idx < G_DIM * I_DIM; idx += 288) {
        int gg = idx / I_DIM;
        int k  = idx - gg * I_DIM;
        Ws[k * WS_STRIDE + gg] = W[idx];
    }
    const float bg = bias[g];

    float* __restrict__ xp_base = &g_xp[dir][0][0][0];

    const int ntiles = (T_DIM * B_DIM) / PROJ_TM;   // 4096
    for (int tile = blockIdx.x; tile < ntiles; tile += gridDim.x) {
        const size_t row0 = (size_t)tile * PROJ_TM;

        __syncthreads();   // prior tile's Xs reads done (also orders Ws on iter 0)
        for (int idx = tid; idx < PROJ_TM * I_DIM; idx += 288) {
            int r = idx / I_DIM;
            int k = idx - r * I_DIM;
            Xs[k * XS_STRIDE + r] = x[(row0 + r) * I_DIM + k];
        }
        __syncthreads();

        float2 acc[PROJ_TM / 2];
        #pragma unroll
        for (int i = 0; i < PROJ_TM / 2; i++) acc[i] = make_float2(bg, bg);

        #pragma unroll 4
        for (int k = 0; k < I_DIM; k++) {
            float w = Ws[k * WS_STRIDE + g];
            float2 wp = make_float2(w, w);
            const float4* xr = reinterpret_cast<const float4*>(&Xs[k * XS_STRIDE]);
            #pragma unroll
            for (int i = 0; i < PROJ_TM / 4; i++) {
                float4 xv = xr[i];
                acc[2 * i]     = ffma2(make_float2(xv.x, xv.y), wp, acc[2 * i]);
                acc[2 * i + 1] = ffma2(make_float2(xv.z, xv.w), wp, acc[2 * i + 1]);
            }
        }

        float* __restrict__ outp = xp_base + row0 * G_DIM + g;
        #pragma unroll
        for (int i = 0; i < PROJ_TM / 2; i++) {
            outp[(size_t)(2 * i)     * G_DIM] = acc[i].x;
            outp[(size_t)(2 * i + 1) * G_DIM] = acc[i].y;
        }
    }
}

// ---------------------------------------------------------------------------
// Kernel 2: GRU scan. grid (64, 2): 8 batch rows per CTA, dir in blockIdx.y.
// Thread g (0..287) owns gate-column g. W_hh column lives in 96 registers.
// h broadcast from smem as [k][r] (2x LDS.128 per k). Rows packed as f32x2.
// Gate phase: thread handles (j = tid%96, r in {tid/96, +3, +6}).
// ---------------------------------------------------------------------------
#define R_PER_CTA 8

__global__ void __launch_bounds__(288, 1)
scan_kernel(const float* __restrict__ whh_f, const float* __restrict__ bhh_f,
            const float* __restrict__ whh_b, const float* __restrict__ bhh_b,
            float* __restrict__ out)
{
    __shared__ __align__(16) float h_s[H_DIM * R_PER_CTA];    // [k][r], k minor-stride 8
    __shared__ float hp_s[R_PER_CTA * G_DIM];                 // [r][g]

    const int dir = blockIdx.y;
    const float* __restrict__ Whh = dir ? whh_b : whh_f;
    const float* __restrict__ bhh = dir ? bhh_b : bhh_f;
    const int tid = threadIdx.x;
    const int g   = tid;                 // 0..287
    const int b0  = blockIdx.x * R_PER_CTA;

    // W_hh column g -> registers (96 regs)
    float wreg[H_DIM];
    {
        const float4* wp = reinterpret_cast<const float4*>(Whh + (size_t)g * H_DIM);
        #pragma unroll
        for (int q = 0; q < H_DIM / 4; q++) {
            float4 v = wp[q];
            wreg[4 * q + 0] = v.x;
            wreg[4 * q + 1] = v.y;
            wreg[4 * q + 2] = v.z;
            wreg[4 * q + 3] = v.w;
        }
    }
    const float bg = bhh[g];

    // h0 = 0
    for (int i = tid; i < H_DIM * R_PER_CTA; i += 288) h_s[i] = 0.0f;

    const int j_g  = tid % 96;   // gate column
    const int r0g  = tid / 96;   // 0,1,2 ; handles rows r0g, r0g+3, r0g+6 (<8)

    __syncthreads();

    const float* __restrict__ xp_dir = &g_xp[dir][0][0][0];

    for (int s = 0; s < T_DIM; s++) {
        const int t = dir ? (T_DIM - 1 - s) : s;
        const float* __restrict__ xpt = xp_dir + ((size_t)t * B_DIM + b0) * G_DIM;

        // Prefetch this step's x-projections (consumed ~2000 cycles later)
        float xr[3], xz[3], xn[3];
        #pragma unroll
        for (int it = 0; it < 3; it++) {
            int r = r0g + 3 * it;
            if (r < R_PER_CTA) {
                const float* p = xpt + (size_t)r * G_DIM + j_g;
                xr[it] = p[0];
                xz[it] = p[96];
                xn[it] = p[192];
            } else {
                xr[it] = 0.f; xz[it] = 0.f; xn[it] = 0.f;
            }
        }

        // Matvec: hp[r][g] = b_hh[g] + sum_k h[r][k] * Whh[g][k]
        float2 a0 = make_float2(bg, bg), a1 = a0, a2 = a0, a3 = a0;
        #pragma unroll
        for (int k = 0; k < H_DIM; k++) {
            float2 wp2 = make_float2(wreg[k], wreg[k]);
            float4 h0 = *reinterpret_cast<const float4*>(&h_s[k * 8]);
            float4 h1 = *reinterpret_cast<const float4*>(&h_s[k * 8 + 4]);
            a0 = ffma2(make_float2(h0.x, h0.y), wp2, a0);
            a1 = ffma2(make_float2(h0.z, h0.w), wp2, a1);
            a2 = ffma2(make_float2(h1.x, h1.y), wp2, a2);
            a3 = ffma2(make_float2(h1.z, h1.w), wp2, a3);
        }
        hp_s[0 * G_DIM + g] = a0.x;
        hp_s[1 * G_DIM + g] = a0.y;
        hp_s[2 * G_DIM + g] = a1.x;
        hp_s[3 * G_DIM + g] = a1.y;
        hp_s[4 * G_DIM + g] = a2.x;
        hp_s[5 * G_DIM + g] = a2.y;
        hp_s[6 * G_DIM + g] = a3.x;
        hp_s[7 * G_DIM + g] = a3.y;

        __syncthreads();   // hp complete before gates read

        // Gates + state update + output
        #pragma unroll
        for (int it = 0; it < 3; it++) {
            int r = r0g + 3 * it;
            if (r < R_PER_CTA) {
                float hr = hp_s[r * G_DIM + j_g];
                float hz = hp_s[r * G_DIM + j_g + 96];
                float hn = hp_s[r * G_DIM + j_g + 192];
                float rg = sigmoidf_fast(xr[it] + hr);
                float zg = sigmoidf_fast(xz[it] + hz);
                float ng = tanhf_fast(xn[it] + rg * hn);
                float hold = h_s[j_g * 8 + r];
                float hnew = ng + zg * (hold - ng);
                h_s[j_g * 8 + r] = hnew;   // own slot: race-free within phase
                out[((size_t)t * B_DIM + b0 + r) * (2 * H_DIM) + dir * H_DIM + j_g] = hnew;
            }
        }

        __syncthreads();   // h updated before next step's matvec
    }
}

// ---------------------------------------------------------------------------
extern "C" void kernel_launch(void* const* d_in, const int* in_sizes, int n_in,
                              void* d_out, int out_size)
{
    const float* x      = (const float*)d_in[0];
    const float* w_ih_f = (const float*)d_in[1];
    const float* w_hh_f = (const float*)d_in[2];
    const float* b_ih_f = (const float*)d_in[3];
    const float* b_hh_f = (const float*)d_in[4];
    const float* w_ih_b = (const float*)d_in[5];
    const float* w_hh_b = (const float*)d_in[6];
    const float* b_ih_b = (const float*)d_in[7];
    const float* b_hh_b = (const float*)d_in[8];
    float* out = (float*)d_out;

    const int smem_proj = (I_DIM * WS_STRIDE + I_DIM * XS_STRIDE) * sizeof(float); // ~142.8 KB
    cudaFuncSetAttribute(proj_kernel, cudaFuncAttributeMaxDynamicSharedMemorySize, smem_proj);

    proj_kernel<<<dim3(148, 2), 288, smem_proj>>>(x, w_ih_f, b_ih_f, w_ih_b, b_ih_b);
    scan_kernel<<<dim3(B_DIM / R_PER_CTA, 2), 288>>>(w_hh_f, b_hh_f, w_hh_b, b_hh_b, out);
}

// round 8
// speedup vs baseline: 1.2203x; 1.2203x over previous
#include <cuda_runtime.h>
#include <cstdint>

#define T_DIM 512
#define B_DIM 512
#define I_DIM 100
#define H_DIM 96
#define G_DIM 288   // 3*H

// Scratch for input projections: [dir][t][b][3H]  (604 MB, static device alloc — allowed)
__device__ float g_xp[2][T_DIM][B_DIM][G_DIM];

// ---------------------------------------------------------------------------
// packed f32x2 FMA (Blackwell)
// ---------------------------------------------------------------------------
__device__ __forceinline__ float2 ffma2(float2 a, float2 b, float2 c) {
    float2 d;
    asm("fma.rn.f32x2 %0, %1, %2, %3;"
        : "=l"(*reinterpret_cast<unsigned long long*>(&d))
        : "l"(*reinterpret_cast<unsigned long long*>(&a)),
          "l"(*reinterpret_cast<unsigned long long*>(&b)),
          "l"(*reinterpret_cast<unsigned long long*>(&c)));
    return d;
}

__device__ __forceinline__ float sigmoidf_fast(float x) {
    return __fdividef(1.0f, 1.0f + __expf(-x));
}
__device__ __forceinline__ float tanhf_fast(float x) {
    return 2.0f * __fdividef(1.0f, 1.0f + __expf(-2.0f * x)) - 1.0f;
}

// ---------------------------------------------------------------------------
// Kernel 1: input projection, G split across 2 CTAs for 2 CTAs/SM.
// grid (74, dir=2, ghalf=2) = 296 CTAs, block 288.
// Thread = (gl in [0,144), rh in {0,1}): column ghalf*144+gl, rows rh*32..+32
// of a 64-row tile. Ws [100][145] (58KB) + Xs [100][68] (27.2KB) = 85.2KB.
// ---------------------------------------------------------------------------
#define PROJ_TM 64
#define GH 144
#define WS2_STRIDE 145
#define XS_STRIDE 68

extern __shared__ float proj_sm[];

__global__ void __launch_bounds__(288, 2)
proj_kernel(const float* __restrict__ x,
            const float* __restrict__ w_f, const float* __restrict__ b_f,
            const float* __restrict__ w_b, const float* __restrict__ b_b)
{
    float* Ws = proj_sm;                        // [100][145]
    float* Xs = proj_sm + I_DIM * WS2_STRIDE;   // [100][68]

    const int dir   = blockIdx.y;
    const int ghalf = blockIdx.z;
    const float* __restrict__ W    = dir ? w_b : w_f;
    const float* __restrict__ bias = dir ? b_b : b_f;
    const int tid = threadIdx.x;
    const int gl  = tid % GH;         // local column
    const int rh  = tid / GH;         // row half (0,1)
    const int g   = ghalf * GH + gl;  // global gate column

    // Load this CTA's 144 W columns transposed: Ws[k][gg] = W[ghalf*144+gg][k]
    for (int idx = tid; idx < GH * I_DIM; idx += 288) {
        int gg = idx / I_DIM;
        int k  = idx - gg * I_DIM;
        Ws[k * WS2_STRIDE + gg] = W[(size_t)(ghalf * GH + gg) * I_DIM + k];
    }
    const float bg = bias[g];

    float* __restrict__ xp_base = &g_xp[dir][0][0][0];

    const int ntiles = (T_DIM * B_DIM) / PROJ_TM;   // 4096
    for (int tile = blockIdx.x; tile < ntiles; tile += gridDim.x) {
        const size_t row0 = (size_t)tile * PROJ_TM;

        __syncthreads();   // prior tile's Xs reads done (also orders Ws on iter 0)
        for (int idx = tid; idx < PROJ_TM * I_DIM; idx += 288) {
            int r = idx / I_DIM;
            int k = idx - r * I_DIM;
            Xs[k * XS_STRIDE + r] = x[(row0 + r) * I_DIM + k];
        }
        __syncthreads();

        float2 acc[16];   // 32 rows packed as f32x2 pairs
        #pragma unroll
        for (int i = 0; i < 16; i++) acc[i] = make_float2(bg, bg);

        #pragma unroll 4
        for (int k = 0; k < I_DIM; k++) {
            float w = Ws[k * WS2_STRIDE + gl];
            float2 wp = make_float2(w, w);
            const float4* xr = reinterpret_cast<const float4*>(&Xs[k * XS_STRIDE + rh * 32]);
            #pragma unroll
            for (int i = 0; i < 8; i++) {
                float4 xv = xr[i];
                acc[2 * i]     = ffma2(make_float2(xv.x, xv.y), wp, acc[2 * i]);
                acc[2 * i + 1] = ffma2(make_float2(xv.z, xv.w), wp, acc[2 * i + 1]);
            }
        }

        float* __restrict__ outp = xp_base + (row0 + rh * 32) * G_DIM + g;
        #pragma unroll
        for (int i = 0; i < 16; i++) {
            outp[(size_t)(2 * i)     * G_DIM] = acc[i].x;
            outp[(size_t)(2 * i + 1) * G_DIM] = acc[i].y;
        }
    }
}

// ---------------------------------------------------------------------------
// Kernel 2: GRU scan, k-split. grid (64, 2), block 576 (18 warps).
// Thread = (g in [0,288), half in {0,1}): owns 48 of column g's 96 k-values
// in registers. Partial sums -> hp_s[half][r][g]; gate phase adds halves.
// Gate items (j in [0,96), r in [0,8)) = 768: thread tid does item tid
// (r=tid/96 in 0..5) and, for tid<192, item tid+576 (r = 6+tid/96, same j).
// ---------------------------------------------------------------------------
#define R_PER_CTA 8
#define KSPLIT 48

__global__ void __launch_bounds__(576, 1)
scan_kernel(const float* __restrict__ whh_f, const float* __restrict__ bhh_f,
            const float* __restrict__ whh_b, const float* __restrict__ bhh_b,
            float* __restrict__ out)
{
    __shared__ __align__(16) float h_s[H_DIM * R_PER_CTA];    // [k][r], 768 floats
    __shared__ float hp_s[2 * R_PER_CTA * G_DIM];             // [half][r][g]

    const int dir = blockIdx.y;
    const float* __restrict__ Whh = dir ? whh_b : whh_f;
    const float* __restrict__ bhh = dir ? bhh_b : bhh_f;
    const int tid  = threadIdx.x;
    const int g    = tid % G_DIM;     // gate column
    const int half = tid / G_DIM;     // k-range half
    const int k0   = half * KSPLIT;
    const int b0   = blockIdx.x * R_PER_CTA;

    // W_hh[g][k0..k0+47] -> registers (48 regs, float4 aligned: k0 in {0,48})
    float wreg[KSPLIT];
    {
        const float4* wp = reinterpret_cast<const float4*>(Whh + (size_t)g * H_DIM + k0);
        #pragma unroll
        for (int q = 0; q < KSPLIT / 4; q++) {
            float4 v = wp[q];
            wreg[4 * q + 0] = v.x;
            wreg[4 * q + 1] = v.y;
            wreg[4 * q + 2] = v.z;
            wreg[4 * q + 3] = v.w;
        }
    }
    const float bg = (half == 0) ? bhh[g] : 0.0f;   // bias counted once

    // h0 = 0 — ALL 768 slots (round-4 bug: single write covered only 576)
    for (int i = tid; i < H_DIM * R_PER_CTA; i += 576) h_s[i] = 0.0f;

    // Gate-item mapping
    const int j    = tid % 96;        // column (same for both items: 576 = 6*96)
    const int r_a  = tid / 96;        // 0..5
    const int r_b  = 6 + tid / 96;    // 6..7, valid only when tid < 192
    const bool has_b = (tid < 192);

    __syncthreads();

    const float* __restrict__ xp_dir = &g_xp[dir][0][0][0];
    float* __restrict__ hp_mine = &hp_s[half * R_PER_CTA * G_DIM + g];

    for (int s = 0; s < T_DIM; s++) {
        const int t = dir ? (T_DIM - 1 - s) : s;
        const float* __restrict__ xpt = xp_dir + ((size_t)t * B_DIM + b0) * G_DIM;

        // Prefetch this step's x-projections (consumed after the matvec)
        float xra, xza, xna, xrb = 0.f, xzb = 0.f, xnb = 0.f;
        {
            const float* p = xpt + (size_t)r_a * G_DIM + j;
            xra = p[0]; xza = p[96]; xna = p[192];
        }
        if (has_b) {
            const float* p = xpt + (size_t)r_b * G_DIM + j;
            xrb = p[0]; xzb = p[96]; xnb = p[192];
        }

        // Partial matvec: hp_half[r][g] = bg? + sum_{k in half} h[r][k]*Whh[g][k]
        float2 a0 = make_float2(bg, bg), a1 = a0, a2 = a0, a3 = a0;
        #pragma unroll
        for (int k = 0; k < KSPLIT; k++) {
            float2 wp2 = make_float2(wreg[k], wreg[k]);
            const float4 h0 = *reinterpret_cast<const float4*>(&h_s[(k0 + k) * 8]);
            const float4 h1 = *reinterpret_cast<const float4*>(&h_s[(k0 + k) * 8 + 4]);
            a0 = ffma2(make_float2(h0.x, h0.y), wp2, a0);
            a1 = ffma2(make_float2(h0.z, h0.w), wp2, a1);
            a2 = ffma2(make_float2(h1.x, h1.y), wp2, a2);
            a3 = ffma2(make_float2(h1.z, h1.w), wp2, a3);
        }
        hp_mine[0 * G_DIM] = a0.x;
        hp_mine[1 * G_DIM] = a0.y;
        hp_mine[2 * G_DIM] = a1.x;
        hp_mine[3 * G_DIM] = a1.y;
        hp_mine[4 * G_DIM] = a2.x;
        hp_mine[5 * G_DIM] = a2.y;
        hp_mine[6 * G_DIM] = a3.x;
        hp_mine[7 * G_DIM] = a3.y;

        __syncthreads();   // partials complete before gates read

        // Gates + state update + output (item a: all threads, r_a in 0..5)
        {
            const float* h0p = &hp_s[r_a * G_DIM + j];
            const float* h1p = &hp_s[(R_PER_CTA + r_a) * G_DIM + j];
            float hr = h0p[0]   + h1p[0];
            float hz = h0p[96]  + h1p[96];
            float hn = h0p[192] + h1p[192];
            float rg = sigmoidf_fast(xra + hr);
            float zg = sigmoidf_fast(xza + hz);
            float ng = tanhf_fast(xna + rg * hn);
            float hold = h_s[j * 8 + r_a];
            float hnew = ng + zg * (hold - ng);
            h_s[j * 8 + r_a] = hnew;
            out[((size_t)t * B_DIM + b0 + r_a) * (2 * H_DIM) + dir * H_DIM + j] = hnew;
        }
        if (has_b) {       // item b: r_b in {6,7}
            const float* h0p = &hp_s[r_b * G_DIM + j];
            const float* h1p = &hp_s[(R_PER_CTA + r_b) * G_DIM + j];
            float hr = h0p[0]   + h1p[0];
            float hz = h0p[96]  + h1p[96];
            float hn = h0p[192] + h1p[192];
            float rg = sigmoidf_fast(xrb + hr);
            float zg = sigmoidf_fast(xzb + hz);
            float ng = tanhf_fast(xnb + rg * hn);
            float hold = h_s[j * 8 + r_b];
            float hnew = ng + zg * (hold - ng);
            h_s[j * 8 + r_b] = hnew;
            out[((size_t)t * B_DIM + b0 + r_b) * (2 * H_DIM) + dir * H_DIM + j] = hnew;
        }

        __syncthreads();   // h updated before next step's matvec
    }
}

// ---------------------------------------------------------------------------
extern "C" void kernel_launch(void* const* d_in, const int* in_sizes, int n_in,
                              void* d_out, int out_size)
{
    const float* x      = (const float*)d_in[0];
    const float* w_ih_f = (const float*)d_in[1];
    const float* w_hh_f = (const float*)d_in[2];
    const float* b_ih_f = (const float*)d_in[3];
    const float* b_hh_f = (const float*)d_in[4];
    const float* w_ih_b = (const float*)d_in[5];
    const float* w_hh_b = (const float*)d_in[6];
    const float* b_ih_b = (const float*)d_in[7];
    const float* b_hh_b = (const float*)d_in[8];
    float* out = (float*)d_out;

    const int smem_proj = (I_DIM * WS2_STRIDE + I_DIM * XS_STRIDE) * sizeof(float); // 85.2 KB
    cudaFuncSetAttribute(proj_kernel, cudaFuncAttributeMaxDynamicSharedMemorySize, smem_proj);

    proj_kernel<<<dim3(74, 2, 2), 288, smem_proj>>>(x, w_ih_f, b_ih_f, w_ih_b, b_ih_b);
    scan_kernel<<<dim3(B_DIM / R_PER_CTA, 2), 576>>>(w_hh_f, b_hh_f, w_hh_b, b_hh_b, out);
}

// round 9
// speedup vs baseline: 1.4712x; 1.2056x over previous
#include <cuda_runtime.h>
#include <cstdint>

#define T_DIM 512
#define B_DIM 512
#define I_DIM 100
#define H_DIM 96
#define G_DIM 288   // 3*H

// Scratch for input projections: [dir][t][b][3H]  (604 MB, static device alloc — allowed)
__device__ float g_xp[2][T_DIM][B_DIM][G_DIM];

// ---------------------------------------------------------------------------
// packed f32x2 ops (Blackwell)
// ---------------------------------------------------------------------------
__device__ __forceinline__ float2 ffma2(float2 a, float2 b, float2 c) {
    float2 d;
    asm("fma.rn.f32x2 %0, %1, %2, %3;"
        : "=l"(*reinterpret_cast<unsigned long long*>(&d))
        : "l"(*reinterpret_cast<unsigned long long*>(&a)),
          "l"(*reinterpret_cast<unsigned long long*>(&b)),
          "l"(*reinterpret_cast<unsigned long long*>(&c)));
    return d;
}
__device__ __forceinline__ float2 fadd2(float2 a, float2 b) {
    float2 d;
    asm("add.rn.f32x2 %0, %1, %2;"
        : "=l"(*reinterpret_cast<unsigned long long*>(&d))
        : "l"(*reinterpret_cast<unsigned long long*>(&a)),
          "l"(*reinterpret_cast<unsigned long long*>(&b)));
    return d;
}

__device__ __forceinline__ float sigmoidf_fast(float x) {
    return __fdividef(1.0f, 1.0f + __expf(-x));
}
__device__ __forceinline__ float tanhf_fast(float x) {
    return 2.0f * __fdividef(1.0f, 1.0f + __expf(-2.0f * x)) - 1.0f;
}

// ---------------------------------------------------------------------------
// Kernel 1: input projection (unchanged from round 8).
// grid (74, dir=2, ghalf=2), block 288, 2 CTAs/SM (85.2 KB smem).
// ---------------------------------------------------------------------------
#define PROJ_TM 64
#define GH 144
#define WS2_STRIDE 145
#define XS_STRIDE 68

extern __shared__ float proj_sm[];

__global__ void __launch_bounds__(288, 2)
proj_kernel(const float* __restrict__ x,
            const float* __restrict__ w_f, const float* __restrict__ b_f,
            const float* __restrict__ w_b, const float* __restrict__ b_b)
{
    float* Ws = proj_sm;                        // [100][145]
    float* Xs = proj_sm + I_DIM * WS2_STRIDE;   // [100][68]

    const int dir   = blockIdx.y;
    const int ghalf = blockIdx.z;
    const float* __restrict__ W    = dir ? w_b : w_f;
    const float* __restrict__ bias = dir ? b_b : b_f;
    const int tid = threadIdx.x;
    const int gl  = tid % GH;
    const int rh  = tid / GH;
    const int g   = ghalf * GH + gl;

    for (int idx = tid; idx < GH * I_DIM; idx += 288) {
        int gg = idx / I_DIM;
        int k  = idx - gg * I_DIM;
        Ws[k * WS2_STRIDE + gg] = W[(size_t)(ghalf * GH + gg) * I_DIM + k];
    }
    const float bg = bias[g];

    float* __restrict__ xp_base = &g_xp[dir][0][0][0];

    const int ntiles = (T_DIM * B_DIM) / PROJ_TM;   // 4096
    for (int tile = blockIdx.x; tile < ntiles; tile += gridDim.x) {
        const size_t row0 = (size_t)tile * PROJ_TM;

        __syncthreads();
        for (int idx = tid; idx < PROJ_TM * I_DIM; idx += 288) {
            int r = idx / I_DIM;
            int k = idx - r * I_DIM;
            Xs[k * XS_STRIDE + r] = x[(row0 + r) * I_DIM + k];
        }
        __syncthreads();

        float2 acc[16];
        #pragma unroll
        for (int i = 0; i < 16; i++) acc[i] = make_float2(bg, bg);

        #pragma unroll 4
        for (int k = 0; k < I_DIM; k++) {
            float w = Ws[k * WS2_STRIDE + gl];
            float2 wp = make_float2(w, w);
            const float4* xr = reinterpret_cast<const float4*>(&Xs[k * XS_STRIDE + rh * 32]);
            #pragma unroll
            for (int i = 0; i < 8; i++) {
                float4 xv = xr[i];
                acc[2 * i]     = ffma2(make_float2(xv.x, xv.y), wp, acc[2 * i]);
                acc[2 * i + 1] = ffma2(make_float2(xv.z, xv.w), wp, acc[2 * i + 1]);
            }
        }

        float* __restrict__ outp = xp_base + (row0 + rh * 32) * G_DIM + g;
        #pragma unroll
        for (int i = 0; i < 16; i++) {
            outp[(size_t)(2 * i)     * G_DIM] = acc[i].x;
            outp[(size_t)(2 * i + 1) * G_DIM] = acc[i].y;
        }
    }
}

// ---------------------------------------------------------------------------
// Kernel 2: single-phase GRU scan. grid (64, 2), block 384 (12 warps).
// Thread = (j in [0,96), kq in [0,4)): owns gate-column triple {j,j+96,j+192}
// over k in {kq + 4i : i<24} (72 W regs), accumulates all 8 rows (12 f32x2).
// kq partners are warp-local (tid = j*4+kq): butterfly all-reduce over 4
// lanes, then lane kq computes gates for rows {2kq, 2kq+1} fully in
// registers. h double-buffered in smem -> ONE barrier per step.
// k-stride-4 assignment makes the 4 lanes' LDS.128 hit disjoint bank quads.
// ---------------------------------------------------------------------------
#define R_PER_CTA 8
#define KPT 24   // k-values per thread

__global__ void __launch_bounds__(384, 1)
scan_kernel(const float* __restrict__ whh_f, const float* __restrict__ bhh_f,
            const float* __restrict__ whh_b, const float* __restrict__ bhh_b,
            float* __restrict__ out)
{
    __shared__ __align__(16) float h_s[2][H_DIM * R_PER_CTA];   // double-buffered [k][r]

    const int dir = blockIdx.y;
    const float* __restrict__ Whh = dir ? whh_b : whh_f;
    const float* __restrict__ bhh = dir ? bhh_b : bhh_f;
    const int tid = threadIdx.x;
    const int j   = tid >> 2;          // 0..95  (gate triple)
    const int kq  = tid & 3;           // 0..3   (k quarter, warp-local lanes)
    const int b0  = blockIdx.x * R_PER_CTA;
    const int r0  = 2 * kq;            // rows owned in the gate phase

    // W_hh columns j / j+96 / j+192 at k = kq + 4i  -> 72 registers
    float wr[KPT], wz[KPT], wn[KPT];
    #pragma unroll
    for (int i = 0; i < KPT; i++) {
        int k = kq + 4 * i;
        wr[i] = Whh[(size_t)j * H_DIM + k];
        wz[i] = Whh[(size_t)(j + 96) * H_DIM + k];
        wn[i] = Whh[(size_t)(j + 192) * H_DIM + k];
    }
    const float br = (kq == 0) ? bhh[j]       : 0.0f;   // bias counted once
    const float bz = (kq == 0) ? bhh[j + 96]  : 0.0f;
    const float bn = (kq == 0) ? bhh[j + 192] : 0.0f;

    // h0 = 0 (both buffers) + register-resident h_old
    for (int i = tid; i < 2 * H_DIM * R_PER_CTA; i += 384)
        (&h_s[0][0])[i] = 0.0f;
    float hold0 = 0.0f, hold1 = 0.0f;
    __syncthreads();

    const float* __restrict__ xp_dir = &g_xp[dir][0][0][0];

    for (int s = 0; s < T_DIM; s++) {
        const int t = dir ? (T_DIM - 1 - s) : s;

        // Prefetch x-projections for this thread's 2 rows (consumed post-matvec)
        const float* __restrict__ p0 =
            xp_dir + ((size_t)t * B_DIM + b0 + r0) * G_DIM + j;
        const float* __restrict__ p1 = p0 + G_DIM;
        float xr0 = p0[0], xz0 = p0[96], xn0 = p0[192];
        float xr1 = p1[0], xz1 = p1[96], xn1 = p1[192];

        // Partial matvec over k = kq+4i for all 8 rows, 3 gate columns
        const float* __restrict__ hb = h_s[s & 1];
        float2 ar0 = make_float2(br, br), ar1 = ar0, ar2 = ar0, ar3 = ar0;
        float2 az0 = make_float2(bz, bz), az1 = az0, az2 = az0, az3 = az0;
        float2 an0 = make_float2(bn, bn), an1 = an0, an2 = an0, an3 = an0;
        #pragma unroll
        for (int i = 0; i < KPT; i++) {
            int k = kq + 4 * i;
            float4 hA = *reinterpret_cast<const float4*>(&hb[k * 8]);
            float4 hB = *reinterpret_cast<const float4*>(&hb[k * 8 + 4]);
            float2 h01 = make_float2(hA.x, hA.y);
            float2 h23 = make_float2(hA.z, hA.w);
            float2 h45 = make_float2(hB.x, hB.y);
            float2 h67 = make_float2(hB.z, hB.w);
            float2 w2;
            w2 = make_float2(wr[i], wr[i]);
            ar0 = ffma2(h01, w2, ar0); ar1 = ffma2(h23, w2, ar1);
            ar2 = ffma2(h45, w2, ar2); ar3 = ffma2(h67, w2, ar3);
            w2 = make_float2(wz[i], wz[i]);
            az0 = ffma2(h01, w2, az0); az1 = ffma2(h23, w2, az1);
            az2 = ffma2(h45, w2, az2); az3 = ffma2(h67, w2, az3);
            w2 = make_float2(wn[i], wn[i]);
            an0 = ffma2(h01, w2, an0); an1 = ffma2(h23, w2, an1);
            an2 = ffma2(h45, w2, an2); an3 = ffma2(h67, w2, an3);
        }

        // Butterfly all-reduce over the 4 kq lanes (warp-local)
        #define RED2(v, m)                                            \
            { float2 _o;                                              \
              _o.x = __shfl_xor_sync(0xFFFFFFFFu, (v).x, (m));        \
              _o.y = __shfl_xor_sync(0xFFFFFFFFu, (v).y, (m));        \
              (v) = fadd2((v), _o); }
        RED2(ar0, 1) RED2(ar1, 1) RED2(ar2, 1) RED2(ar3, 1)
        RED2(az0, 1) RED2(az1, 1) RED2(az2, 1) RED2(az3, 1)
        RED2(an0, 1) RED2(an1, 1) RED2(an2, 1) RED2(an3, 1)
        RED2(ar0, 2) RED2(ar1, 2) RED2(ar2, 2) RED2(ar3, 2)
        RED2(az0, 2) RED2(az1, 2) RED2(az2, 2) RED2(az3, 2)
        RED2(an0, 2) RED2(an1, 2) RED2(an2, 2) RED2(an3, 2)
        #undef RED2

        // Lane kq takes row-pair kq (uniform-per-thread select -> FSELs)
        float2 vr = (kq & 2) ? ((kq & 1) ? ar3 : ar2) : ((kq & 1) ? ar1 : ar0);
        float2 vz = (kq & 2) ? ((kq & 1) ? az3 : az2) : ((kq & 1) ? az1 : az0);
        float2 vn = (kq & 2) ? ((kq & 1) ? an3 : an2) : ((kq & 1) ? an1 : an0);

        // Gates for rows r0, r0+1 — entirely in registers
        float rg0 = sigmoidf_fast(xr0 + vr.x);
        float zg0 = sigmoidf_fast(xz0 + vz.x);
        float ng0 = tanhf_fast(xn0 + rg0 * vn.x);
        float hn0 = ng0 + zg0 * (hold0 - ng0);
        float rg1 = sigmoidf_fast(xr1 + vr.y);
        float zg1 = sigmoidf_fast(xz1 + vz.y);
        float ng1 = tanhf_fast(xn1 + rg1 * vn.y);
        float hn1 = ng1 + zg1 * (hold1 - ng1);
        hold0 = hn0;
        hold1 = hn1;

        // Write next-state buffer (parity s+1) + output
        float* __restrict__ hw = h_s[(s + 1) & 1];
        *reinterpret_cast<float2*>(&hw[j * 8 + r0]) = make_float2(hn0, hn1);

        float* __restrict__ op =
            out + ((size_t)t * B_DIM + b0 + r0) * (2 * H_DIM) + dir * H_DIM + j;
        op[0]         = hn0;
        op[2 * H_DIM] = hn1;

        __syncthreads();   // buffer (s+1) complete; buffer s reads all done
    }
}

// ---------------------------------------------------------------------------
extern "C" void kernel_launch(void* const* d_in, const int* in_sizes, int n_in,
                              void* d_out, int out_size)
{
    const float* x      = (const float*)d_in[0];
    const float* w_ih_f = (const float*)d_in[1];
    const float* w_hh_f = (const float*)d_in[2];
    const float* b_ih_f = (const float*)d_in[3];
    const float* b_hh_f = (const float*)d_in[4];
    const float* w_ih_b = (const float*)d_in[5];
    const float* w_hh_b = (const float*)d_in[6];
    const float* b_ih_b = (const float*)d_in[7];
    const float* b_hh_b = (const float*)d_in[8];
    float* out = (float*)d_out;

    const int smem_proj = (I_DIM * WS2_STRIDE + I_DIM * XS_STRIDE) * sizeof(float); // 85.2 KB
    cudaFuncSetAttribute(proj_kernel, cudaFuncAttributeMaxDynamicSharedMemorySize, smem_proj);

    proj_kernel<<<dim3(74, 2, 2), 288, smem_proj>>>(x, w_ih_f, b_ih_f, w_ih_b, b_ih_b);
    scan_kernel<<<dim3(B_DIM / R_PER_CTA, 2), 384>>>(w_hh_f, b_hh_f, w_hh_b, b_hh_b, out);
}